// round 13
// baseline (speedup 1.0000x reference)
#include <cuda_runtime.h>
#include <math.h>

#define NN 8192
#define EE 131072
#define DIM 32
#define HID 128
#define BG 64
#define NMP 3
#define S2S 3
#define KDIM 4096   // HID*DIM

typedef unsigned long long ull;

__device__ __forceinline__ ull pk2(float lo, float hi) {
    ull r; asm("mov.b64 %0,{%1,%2};" : "=l"(r) : "f"(lo), "f"(hi)); return r;
}
__device__ __forceinline__ float2 upk2(ull v) {
    float2 r; asm("mov.b64 {%0,%1},%2;" : "=f"(r.x), "=f"(r.y) : "l"(v)); return r;
}
__device__ __forceinline__ ull ffma2(ull a, ull b, ull c) {
    ull d; asm("fma.rn.f32x2 %0,%1,%2,%3;" : "=l"(d) : "l"(a), "l"(b), "l"(c)); return d;
}
__device__ __forceinline__ ull add2(ull a, ull b) {
    ull d; asm("add.rn.f32x2 %0,%1,%2;" : "=l"(d) : "l"(a), "l"(b)); return d;
}

// ---------------- scratch (device globals; no allocation) ----------------
__device__ float g_out[NN * DIM];            // node features / GRU hidden
__device__ float g_V[(size_t)NN * KDIM];     // V[s][k][o]
__device__ float g_agg[NN * DIM];            // atomic message accum (re-zeroed by k_update)
__device__ int   g_cnt[NN];
__device__ int   g_dcnt[NN];
__device__ int   g_rowptr[NN + 1];
__device__ int   g_woff[NN];
__device__ int   g_eids[EE];
__device__ float g_deg[NN];
__device__ int   g_gptr[BG + 1];
__device__ float g_qh[BG * DIM];
__device__ float g_qc[BG * DIM];
__device__ float g_qstar[BG * 2 * DIM];

__device__ __forceinline__ float sigm(float x) { return 1.0f / (1.0f + expf(-x)); }

// ---------------- setup ----------------
__global__ void k_zeroinit(const float* __restrict__ x,
                           const float* __restrict__ w0,
                           const float* __restrict__ b0) {
    int idx = blockIdx.x * blockDim.x + threadIdx.x;
    if (idx < NN) { g_cnt[idx] = 0; g_dcnt[idx] = 0; }
    if (idx < NN * DIM) {
        int n = idx >> 5, j = idx & 31;
        float v = x[n] * w0[j] + b0[j];
        g_out[idx] = v > 0.f ? v : 0.f;
    }
}

// 1 edge/thread, 512 blocks: max warps in flight to hide atomic latency
__global__ void k_count(const int* __restrict__ ei) {
    int e = blockIdx.x * blockDim.x + threadIdx.x;
    if (e < EE) {
        atomicAdd(&g_cnt[ei[e]], 1);          // src (CSR grouping)
        atomicAdd(&g_dcnt[ei[EE + e]], 1);    // dst (degree for mean)
    }
}

// shfl-based exclusive scan of src counts -> rowptr/woff; deg from dcnt
__global__ void k_scan() {
    __shared__ int wsum[32], wscan[32];
    int t = threadIdx.x, lane = t & 31, wid = t >> 5;
    int base = t * 8;
    int v[8]; int csum = 0;
#pragma unroll
    for (int i = 0; i < 8; i++) { v[i] = g_cnt[base + i]; csum += v[i]; }
    int inc = csum;
#pragma unroll
    for (int off = 1; off < 32; off <<= 1) {
        int nv = __shfl_up_sync(0xffffffffu, inc, off);
        if (lane >= off) inc += nv;
    }
    if (lane == 31) wsum[wid] = inc;
    __syncthreads();
    if (t < 32) {
        int w = wsum[t];
#pragma unroll
        for (int off = 1; off < 32; off <<= 1) {
            int nv = __shfl_up_sync(0xffffffffu, w, off);
            if (t >= off) w += nv;
        }
        wscan[t] = w;
    }
    __syncthreads();
    int run = inc - csum + (wid > 0 ? wscan[wid - 1] : 0);
#pragma unroll
    for (int i = 0; i < 8; i++) {
        g_rowptr[base + i] = run;
        g_woff[base + i] = run;
        run += v[i];
    }
    if (t == 1023) g_rowptr[NN] = run;
#pragma unroll
    for (int i = 0; i < 8; i++) {
        int d = g_dcnt[base + i];
        g_deg[base + i] = (float)(d > 0 ? d : 1);
    }
}

// CSR fill, 1 edge/thread (+ per-graph ranges in block 0)
__global__ void k_fill(const int* __restrict__ ei, const int* __restrict__ batch) {
    int e = blockIdx.x * blockDim.x + threadIdx.x;
    if (e < EE) {
        int src = ei[e];
        int pos = atomicAdd(&g_woff[src], 1);
        g_eids[pos] = e;
    }
    if (blockIdx.x == 0 && threadIdx.x <= BG) {
        int b = threadIdx.x;
        int lo = 0, hi = NN;
        while (lo < hi) {
            int mid = (lo + hi) >> 1;
            if (batch[mid] < b) lo = mid + 1; else hi = mid;
        }
        g_gptr[b] = lo;
    }
}

// ---------------- V GEMM: V[N,4096] = out[N,32] @ B[32,4096] ----------------
// grid 2048 = 128 node-tiles x 16 r-chunks (256 cols each); block 256.
// A staged [d][n] (66 pad) so each thread reads node-PAIRS via broadcast LDS.128.
__global__ void k_vgemm(const float* __restrict__ w2) {
    __shared__ ull  At2[32][66];    // [d][n] pk2(a,a)  16.5KB
    __shared__ float Bs[32][256];   // [d][rr]          32KB
    int tid = threadIdx.x;
    int ntile = blockIdx.x & 127;
    int rchunk = blockIdx.x >> 7;
    int rbase = rchunk * 256;
    int nodebase = ntile * 64;

#pragma unroll
    for (int i = 0; i < 8; i++) {
        int s = i * 256 + tid;
        int n = s >> 5, d = s & 31;          // coalesced LDG; 4-way-conflict STS (ok)
        float a = g_out[(nodebase + n) * DIM + d];
        At2[d][n] = pk2(a, a);
    }
#pragma unroll
    for (int i = 0; i < 8; i++) {
        int s = i * 256 + tid;
        int d = s >> 6, rq = s & 63;
        int r = rbase + rq * 4;
        int k = r >> 5, o = r & 31;
        *(float4*)&Bs[d][rq * 4] = *(const float4*)&w2[(size_t)k * 1024 + d * 32 + o];
    }
    __syncthreads();

    int w = tid >> 5, l = tid & 31;
    // thread owns nodes {2w+16jj, 2w+16jj+1} jj=0..3, col-pairs {rbase+64q+2l}
    ull acc[4][2][4];
#pragma unroll
    for (int jj = 0; jj < 4; jj++)
#pragma unroll
        for (int c = 0; c < 2; c++)
#pragma unroll
            for (int q = 0; q < 4; q++) acc[jj][c][q] = 0ull;

#pragma unroll 4
    for (int d = 0; d < 32; d++) {
        ull b0 = *(const ull*)&Bs[d][2 * l];
        ull b1 = *(const ull*)&Bs[d][64 + 2 * l];
        ull b2 = *(const ull*)&Bs[d][128 + 2 * l];
        ull b3 = *(const ull*)&Bs[d][192 + 2 * l];
#pragma unroll
        for (int jj = 0; jj < 4; jj++) {
            ulonglong2 ap = *(const ulonglong2*)&At2[d][2 * w + 16 * jj];
            acc[jj][0][0] = ffma2(ap.x, b0, acc[jj][0][0]);
            acc[jj][0][1] = ffma2(ap.x, b1, acc[jj][0][1]);
            acc[jj][0][2] = ffma2(ap.x, b2, acc[jj][0][2]);
            acc[jj][0][3] = ffma2(ap.x, b3, acc[jj][0][3]);
            acc[jj][1][0] = ffma2(ap.y, b0, acc[jj][1][0]);
            acc[jj][1][1] = ffma2(ap.y, b1, acc[jj][1][1]);
            acc[jj][1][2] = ffma2(ap.y, b2, acc[jj][1][2]);
            acc[jj][1][3] = ffma2(ap.y, b3, acc[jj][1][3]);
        }
    }
#pragma unroll
    for (int jj = 0; jj < 4; jj++)
#pragma unroll
        for (int c = 0; c < 2; c++) {
            int n = nodebase + 2 * w + 16 * jj + c;
            float* Vr = g_V + (size_t)n * KDIM + rbase;
#pragma unroll
            for (int q = 0; q < 4; q++) {
                float2 v = upk2(acc[jj][c][q]);
                *(float2*)&Vr[64 * q + 2 * l] = v;
            }
        }
}

// ---------------- edge contraction + scatter (per src node) ----------------
// Frozen R11 structure; only change: V preload issued first (ILP ahead of ub).
__global__ void k_edges(const int* __restrict__ ei, const float* __restrict__ ea,
                        const float* __restrict__ w1, const float* __restrict__ b1,
                        const float* __restrict__ b2) {
    __shared__ float su[DIM];
    __shared__ float2 sea[8];
    __shared__ int sdst[8];
    __shared__ ull sh[4][HID];
    __shared__ ull red[16 * 33];
    int s = blockIdx.x;
    int lo = g_rowptr[s], hi = g_rowptr[s + 1];
    if (lo >= hi) return;
    int t = threadIdx.x;
    int kq = t >> 5, o = t & 31;

    // V preload first: 32 long-latency LDGs in flight ASAP
    ull vp[32];
    const float* Vs = g_V + (size_t)s * KDIM + kq * 32 * 32 + o;
#pragma unroll
    for (int kk = 0; kk < 32; kk++) {
        float v = Vs[kk * 32];
        vp[kk] = pk2(v, v);
    }

    float w1c0 = __ldg(&w1[t]), w1c1 = __ldg(&w1[HID + t]), b1c = __ldg(&b1[t]);
    if (t < DIM) su[t] = g_out[s * DIM + t];
    __syncthreads();

    float ub = 0.f;
#pragma unroll
    for (int d = 0; d < DIM; d++) ub += su[d] * __ldg(&b2[d * DIM + o]);

    for (int base = lo; base < hi; base += 8) {
        int m = hi - base; if (m > 8) m = 8;
        __syncthreads();
        if (t < m) {
            int e = g_eids[base + t];
            sea[t] = *(const float2*)&ea[2 * e];
            sdst[t] = ei[EE + e];
        }
        __syncthreads();
#pragma unroll
        for (int p = 0; p < 4; p++) {
            float h0 = 0.f, h1 = 0.f;
            if (2 * p < m) {
                float v = sea[2 * p].x * w1c0 + sea[2 * p].y * w1c1 + b1c;
                h0 = v > 0.f ? v : 0.f;
            }
            if (2 * p + 1 < m) {
                float v = sea[2 * p + 1].x * w1c0 + sea[2 * p + 1].y * w1c1 + b1c;
                h1 = v > 0.f ? v : 0.f;
            }
            sh[p][t] = pk2(h0, h1);
        }
        __syncthreads();
#pragma unroll
        for (int p = 0; p < 4; p++) {
            if (2 * p < m) {
                ull acc0 = 0, acc1 = 0;
                const ulonglong2* shp = (const ulonglong2*)&sh[p][kq * 32];
#pragma unroll
                for (int kk = 0; kk < 16; kk++) {
                    ulonglong2 hh = shp[kk];
                    acc0 = ffma2(hh.x, vp[2 * kk], acc0);
                    acc1 = ffma2(hh.y, vp[2 * kk + 1], acc1);
                }
                red[(p * 4 + kq) * 33 + o] = add2(acc0, acc1);
            }
        }
        __syncthreads();
        {
            int p = kq;
            if (2 * p < m) {
                ull sum = add2(add2(red[(p * 4 + 0) * 33 + o], red[(p * 4 + 1) * 33 + o]),
                               add2(red[(p * 4 + 2) * 33 + o], red[(p * 4 + 3) * 33 + o]));
                float2 ms = upk2(sum);
                atomicAdd(&g_agg[sdst[2 * p] * DIM + o], ms.x + ub);
                if (2 * p + 1 < m) atomicAdd(&g_agg[sdst[2 * p + 1] * DIM + o], ms.y + ub);
            }
        }
    }
}

// ---------------- node update: mean + root + GRU (re-zeroes g_agg) ----------------
// 2 nodes per warp: weight loads (rootw, wih, whh) amortized over both.
__global__ void k_update(const float* __restrict__ rootw,
                         const float* __restrict__ convb,
                         const float* __restrict__ wih,
                         const float* __restrict__ whh,
                         const float* __restrict__ bih,
                         const float* __restrict__ bhh) {
    __shared__ float Msm[16][DIM];
    int wl = threadIdx.x >> 5;          // warp 0..7
    int o = threadIdx.x & 31;
    int n0 = blockIdx.x * 16 + wl * 2;  // nodes n0, n0+1

    float agg0 = g_agg[n0 * DIM + o];
    float agg1 = g_agg[(n0 + 1) * DIM + o];
    g_agg[n0 * DIM + o] = 0.f;
    g_agg[(n0 + 1) * DIM + o] = 0.f;
    float cb = __ldg(&convb[o]);
    float mo0 = agg0 / g_deg[n0] + cb;
    float mo1 = agg1 / g_deg[n0 + 1] + cb;
#pragma unroll
    for (int d = 0; d < DIM; d++) {
        float rw = __ldg(&rootw[d * DIM + o]);
        mo0 += g_out[n0 * DIM + d] * rw;
        mo1 += g_out[(n0 + 1) * DIM + d] * rw;
    }
    mo0 = mo0 > 0.f ? mo0 : 0.f;
    mo1 = mo1 > 0.f ? mo1 : 0.f;
    Msm[wl * 2][o] = mo0;
    Msm[wl * 2 + 1][o] = mo1;
    __syncthreads();

    float bi0 = __ldg(&bih[o]), bi1 = __ldg(&bih[32 + o]), bi2 = __ldg(&bih[64 + o]);
    float bh0 = __ldg(&bhh[o]), bh1 = __ldg(&bhh[32 + o]), bh2 = __ldg(&bhh[64 + o]);
    float ir0 = bi0, iz0 = bi1, in0 = bi2, hr0 = bh0, hz0 = bh1, hn0 = bh2;
    float ir1 = bi0, iz1 = bi1, in1 = bi2, hr1 = bh0, hz1 = bh1, hn1 = bh2;
#pragma unroll
    for (int d = 0; d < DIM; d++) {
        float wi0 = __ldg(&wih[d * 96 + o]);
        float wi1 = __ldg(&wih[d * 96 + 32 + o]);
        float wi2 = __ldg(&wih[d * 96 + 64 + o]);
        float wh0 = __ldg(&whh[d * 96 + o]);
        float wh1 = __ldg(&whh[d * 96 + 32 + o]);
        float wh2 = __ldg(&whh[d * 96 + 64 + o]);
        float md0 = Msm[wl * 2][d];
        float md1 = Msm[wl * 2 + 1][d];
        float hd0 = g_out[n0 * DIM + d];
        float hd1 = g_out[(n0 + 1) * DIM + d];
        ir0 += md0 * wi0; iz0 += md0 * wi1; in0 += md0 * wi2;
        hr0 += hd0 * wh0; hz0 += hd0 * wh1; hn0 += hd0 * wh2;
        ir1 += md1 * wi0; iz1 += md1 * wi1; in1 += md1 * wi2;
        hr1 += hd1 * wh0; hz1 += hd1 * wh1; hn1 += hd1 * wh2;
    }
    float r0 = sigm(ir0 + hr0), z0 = sigm(iz0 + hz0);
    float nv0 = tanhf(in0 + r0 * hn0);
    float r1 = sigm(ir1 + hr1), z1 = sigm(iz1 + hz1);
    float nv1 = tanhf(in1 + r1 * hn1);
    float hold0 = g_out[n0 * DIM + o];
    float hold1 = g_out[(n0 + 1) * DIM + o];
    __syncwarp();
    g_out[n0 * DIM + o] = (1.f - z0) * nv0 + z0 * hold0;
    g_out[(n0 + 1) * DIM + o] = (1.f - z1) * nv1 + z1 * hold1;
}

// ---------------- Set2Set: fused LSTM + attention (+ final MLP on last step) ----------------
__global__ void k_s2s(int step, int last,
                      const float* __restrict__ wih, const float* __restrict__ whh,
                      const float* __restrict__ bih, const float* __restrict__ bhh,
                      const float* __restrict__ l1w, const float* __restrict__ l1b,
                      const float* __restrict__ l2w, const float* __restrict__ l2b,
                      float* __restrict__ yout) {
    __shared__ float gs[128];
    __shared__ float sqh[32];
    __shared__ float rfin[32];
    __shared__ float ebuf[4096];
    __shared__ float wred[8];
    __shared__ float rpart[8][32];
    __shared__ float s_bmax, s_den;
    int b = blockIdx.x;
    int tid = threadIdx.x;
    int w = tid >> 5, lane = tid & 31;

    if (tid < 128) {
        float g = __ldg(&bih[tid]) + __ldg(&bhh[tid]);
        if (step > 0) {
#pragma unroll
            for (int t = 0; t < 2 * DIM; t++)
                g += g_qstar[b * 2 * DIM + t] * __ldg(&wih[t * 128 + tid]);
#pragma unroll
            for (int t = 0; t < DIM; t++)
                g += g_qh[b * DIM + t] * __ldg(&whh[t * 128 + tid]);
        }
        gs[tid] = g;
    }
    __syncthreads();
    if (tid < 32) {
        float qc_old = (step > 0) ? g_qc[b * DIM + tid] : 0.f;
        float qc = sigm(gs[32 + tid]) * qc_old + sigm(gs[tid]) * tanhf(gs[64 + tid]);
        g_qc[b * DIM + tid] = qc;
        float qh = sigm(gs[96 + tid]) * tanhf(qc);
        g_qh[b * DIM + tid] = qh;
        sqh[tid] = qh;
    }
    __syncthreads();

    int lo = g_gptr[b], hi = g_gptr[b + 1];
    int cnt = hi - lo;

    float mymax = -1e30f;
    for (int i = lo + w; i < hi; i += 8) {
        float v = g_out[(size_t)i * DIM + lane] * sqh[lane];
#pragma unroll
        for (int off = 16; off; off >>= 1) v += __shfl_xor_sync(0xffffffffu, v, off);
        if (lane == 0) ebuf[i - lo] = v;
        mymax = fmaxf(mymax, v);
    }
    if (lane == 0) wred[w] = mymax;
    __syncthreads();
    if (tid == 0) {
        float m = -1e30f;
        for (int q = 0; q < 8; q++) m = fmaxf(m, wred[q]);
        s_bmax = m;
    }
    __syncthreads();
    float bm = s_bmax;

    float ssum = 0.f;
    for (int idx = tid; idx < cnt; idx += 256) {
        float ev = expf(ebuf[idx] - bm);
        ebuf[idx] = ev;
        ssum += ev;
    }
#pragma unroll
    for (int off = 16; off; off >>= 1) ssum += __shfl_xor_sync(0xffffffffu, ssum, off);
    if (lane == 0) wred[w] = ssum;
    __syncthreads();
    if (tid == 0) {
        float tt = 0.f;
        for (int q = 0; q < 8; q++) tt += wred[q];
        s_den = tt;
    }
    __syncthreads();
    float invden = (cnt > 0 && s_den > 0.f) ? 1.f / s_den : 0.f;

    float rl = 0.f;
    for (int i = lo + w; i < hi; i += 8) {
        float a = ebuf[i - lo] * invden;
        rl += a * g_out[(size_t)i * DIM + lane];
    }
    rpart[w][lane] = rl;
    __syncthreads();
    if (w == 0) {
        float r = 0.f;
#pragma unroll
        for (int q = 0; q < 8; q++) r += rpart[q][lane];
        rfin[lane] = r;
        g_qstar[b * 2 * DIM + 32 + lane] = r;
        g_qstar[b * 2 * DIM + lane] = sqh[lane];
    }

    if (last) {
        __syncthreads();
        if (tid < 32) {
            int j = tid;
            float hj = __ldg(&l1b[j]);
#pragma unroll
            for (int t = 0; t < DIM; t++) hj += sqh[t] * __ldg(&l1w[t * DIM + j]);
#pragma unroll
            for (int t = 0; t < DIM; t++) hj += rfin[t] * __ldg(&l1w[(DIM + t) * DIM + j]);
            hj = hj > 0.f ? hj : 0.f;
            float v = hj * __ldg(&l2w[j]);
#pragma unroll
            for (int off = 16; off; off >>= 1) v += __shfl_xor_sync(0xffffffffu, v, off);
            if (j == 0) yout[b] = v + __ldg(&l2b[0]);
        }
    }
}

// ---------------- launch ----------------
extern "C" void kernel_launch(void* const* d_in, const int* in_sizes, int n_in,
                              void* d_out, int out_size) {
    const float* x       = (const float*)d_in[0];
    const float* ea      = (const float*)d_in[1];
    const float* lin0w   = (const float*)d_in[2];
    const float* lin0b   = (const float*)d_in[3];
    const float* ennw1   = (const float*)d_in[4];
    const float* ennb1   = (const float*)d_in[5];
    const float* ennw2   = (const float*)d_in[6];
    const float* ennb2   = (const float*)d_in[7];
    const float* rootw   = (const float*)d_in[8];
    const float* convb   = (const float*)d_in[9];
    const float* gruwih  = (const float*)d_in[10];
    const float* gruwhh  = (const float*)d_in[11];
    const float* grubih  = (const float*)d_in[12];
    const float* grubhh  = (const float*)d_in[13];
    const float* s2swih  = (const float*)d_in[14];
    const float* s2swhh  = (const float*)d_in[15];
    const float* s2sbih  = (const float*)d_in[16];
    const float* s2sbhh  = (const float*)d_in[17];
    const float* lin1w   = (const float*)d_in[18];
    const float* lin1b   = (const float*)d_in[19];
    const float* lin2w   = (const float*)d_in[20];
    const float* lin2b   = (const float*)d_in[21];
    const int*   ei      = (const int*)d_in[22];
    const int*   batch   = (const int*)d_in[23];
    float* yout = (float*)d_out;

    k_zeroinit<<<(NN * DIM + 1023) / 1024, 1024>>>(x, lin0w, lin0b);
    k_count<<<(EE + 255) / 256, 256>>>(ei);
    k_scan<<<1, 1024>>>();
    k_fill<<<(EE + 255) / 256, 256>>>(ei, batch);

    for (int it = 0; it < NMP; it++) {
        k_vgemm<<<2048, 256>>>(ennw2);
        k_edges<<<NN, 128>>>(ei, ea, ennw1, ennb1, ennb2);
        k_update<<<NN / 16, 256>>>(rootw, convb, gruwih, gruwhh, grubih, grubhh);
    }

    for (int s = 0; s < S2S; s++) {
        k_s2s<<<BG, 256>>>(s, s == S2S - 1 ? 1 : 0,
                           s2swih, s2swhh, s2sbih, s2sbhh,
                           lin1w, lin1b, lin2w, lin2b, yout);
    }
}

// round 14
// speedup vs baseline: 1.0440x; 1.0440x over previous
#include <cuda_runtime.h>
#include <math.h>

#define NN 8192
#define EE 131072
#define DIM 32
#define HID 128
#define BG 64
#define NMP 3
#define S2S 3
#define KDIM 4096   // HID*DIM

typedef unsigned long long ull;

__device__ __forceinline__ ull pk2(float lo, float hi) {
    ull r; asm("mov.b64 %0,{%1,%2};" : "=l"(r) : "f"(lo), "f"(hi)); return r;
}
__device__ __forceinline__ float2 upk2(ull v) {
    float2 r; asm("mov.b64 {%0,%1},%2;" : "=f"(r.x), "=f"(r.y) : "l"(v)); return r;
}
__device__ __forceinline__ ull ffma2(ull a, ull b, ull c) {
    ull d; asm("fma.rn.f32x2 %0,%1,%2,%3;" : "=l"(d) : "l"(a), "l"(b), "l"(c)); return d;
}
__device__ __forceinline__ ull add2(ull a, ull b) {
    ull d; asm("add.rn.f32x2 %0,%1,%2;" : "=l"(d) : "l"(a), "l"(b)); return d;
}

// ---------------- scratch (device globals; no allocation) ----------------
__device__ float g_out[NN * DIM];            // node features / GRU hidden
__device__ float g_V[(size_t)NN * KDIM];     // V[s][k][o]
__device__ float g_agg[NN * DIM];            // atomic message accum (re-zeroed by k_update)
__device__ int   g_cnt[NN];
__device__ int   g_dcnt[NN];
__device__ int   g_rowptr[NN + 1];
__device__ int   g_woff[NN];
__device__ int   g_eids[EE];
__device__ float g_deg[NN];
__device__ int   g_gptr[BG + 1];
__device__ float g_qh[BG * DIM];
__device__ float g_qc[BG * DIM];
__device__ float g_qstar[BG * 2 * DIM];

__device__ __forceinline__ float sigm(float x) { return 1.0f / (1.0f + expf(-x)); }

// ---------------- setup ----------------
__global__ void k_zeroinit(const float* __restrict__ x,
                           const float* __restrict__ w0,
                           const float* __restrict__ b0) {
    int idx = blockIdx.x * blockDim.x + threadIdx.x;
    if (idx < NN) { g_cnt[idx] = 0; g_dcnt[idx] = 0; }
    if (idx < NN * DIM) {
        int n = idx >> 5, j = idx & 31;
        float v = x[n] * w0[j] + b0[j];
        g_out[idx] = v > 0.f ? v : 0.f;
    }
}

// 1 edge/thread, 512 blocks: max warps in flight to hide atomic latency
__global__ void k_count(const int* __restrict__ ei) {
    int e = blockIdx.x * blockDim.x + threadIdx.x;
    if (e < EE) {
        atomicAdd(&g_cnt[ei[e]], 1);          // src (CSR grouping)
        atomicAdd(&g_dcnt[ei[EE + e]], 1);    // dst (degree for mean)
    }
}

// shfl-based exclusive scan of src counts -> rowptr/woff; deg from dcnt
__global__ void k_scan() {
    __shared__ int wsum[32], wscan[32];
    int t = threadIdx.x, lane = t & 31, wid = t >> 5;
    int base = t * 8;
    int v[8]; int csum = 0;
#pragma unroll
    for (int i = 0; i < 8; i++) { v[i] = g_cnt[base + i]; csum += v[i]; }
    int inc = csum;
#pragma unroll
    for (int off = 1; off < 32; off <<= 1) {
        int nv = __shfl_up_sync(0xffffffffu, inc, off);
        if (lane >= off) inc += nv;
    }
    if (lane == 31) wsum[wid] = inc;
    __syncthreads();
    if (t < 32) {
        int w = wsum[t];
#pragma unroll
        for (int off = 1; off < 32; off <<= 1) {
            int nv = __shfl_up_sync(0xffffffffu, w, off);
            if (t >= off) w += nv;
        }
        wscan[t] = w;
    }
    __syncthreads();
    int run = inc - csum + (wid > 0 ? wscan[wid - 1] : 0);
#pragma unroll
    for (int i = 0; i < 8; i++) {
        g_rowptr[base + i] = run;
        g_woff[base + i] = run;
        run += v[i];
    }
    if (t == 1023) g_rowptr[NN] = run;
#pragma unroll
    for (int i = 0; i < 8; i++) {
        int d = g_dcnt[base + i];
        g_deg[base + i] = (float)(d > 0 ? d : 1);
    }
}

// CSR fill, 1 edge/thread (+ per-graph ranges in block 0)
__global__ void k_fill(const int* __restrict__ ei, const int* __restrict__ batch) {
    int e = blockIdx.x * blockDim.x + threadIdx.x;
    if (e < EE) {
        int src = ei[e];
        int pos = atomicAdd(&g_woff[src], 1);
        g_eids[pos] = e;
    }
    if (blockIdx.x == 0 && threadIdx.x <= BG) {
        int b = threadIdx.x;
        int lo = 0, hi = NN;
        while (lo < hi) {
            int mid = (lo + hi) >> 1;
            if (batch[mid] < b) lo = mid + 1; else hi = mid;
        }
        g_gptr[b] = lo;
    }
}

// ---------------- V GEMM: V[N,4096] = out[N,32] @ B[32,4096] ----------------
// grid 2048 = 128 node-tiles x 16 r-chunks (256 cols each); block 256.
__global__ void k_vgemm(const float* __restrict__ w2) {
    __shared__ ull  At2[64][32];    // [n][d] pk2(a,a)   16KB
    __shared__ float Bs[32][256];   // [d][rr]           32KB
    int tid = threadIdx.x;
    int ntile = blockIdx.x & 127;
    int rchunk = blockIdx.x >> 7;
    int rbase = rchunk * 256;
    int nodebase = ntile * 64;

#pragma unroll
    for (int i = 0; i < 8; i++) {
        int s = i * 256 + tid;
        int n = s >> 5, d = s & 31;
        float a = g_out[(nodebase + n) * DIM + d];
        At2[n][d] = pk2(a, a);
    }
#pragma unroll
    for (int i = 0; i < 8; i++) {
        int s = i * 256 + tid;
        int d = s >> 6, rq = s & 63;
        int r = rbase + rq * 4;
        int k = r >> 5, o = r & 31;
        *(float4*)&Bs[d][rq * 4] = *(const float4*)&w2[(size_t)k * 1024 + d * 32 + o];
    }
    __syncthreads();

    int w = tid >> 5, l = tid & 31;
    ull acc[8][4];
#pragma unroll
    for (int j = 0; j < 8; j++)
#pragma unroll
        for (int q = 0; q < 4; q++) acc[j][q] = 0ull;

#pragma unroll 4
    for (int d = 0; d < 32; d++) {
        ull b0 = *(const ull*)&Bs[d][2 * l];
        ull b1 = *(const ull*)&Bs[d][64 + 2 * l];
        ull b2 = *(const ull*)&Bs[d][128 + 2 * l];
        ull b3 = *(const ull*)&Bs[d][192 + 2 * l];
#pragma unroll
        for (int j = 0; j < 8; j++) {
            ull a = At2[w + 8 * j][d];
            acc[j][0] = ffma2(a, b0, acc[j][0]);
            acc[j][1] = ffma2(a, b1, acc[j][1]);
            acc[j][2] = ffma2(a, b2, acc[j][2]);
            acc[j][3] = ffma2(a, b3, acc[j][3]);
        }
    }
#pragma unroll
    for (int j = 0; j < 8; j++) {
        int n = nodebase + w + 8 * j;
        float* Vr = g_V + (size_t)n * KDIM + rbase;
#pragma unroll
        for (int q = 0; q < 4; q++) {
            float2 v = upk2(acc[j][q]);
            *(float2*)&Vr[64 * q + 2 * l] = v;
        }
    }
}

// ---------------- edge contraction + scatter (per src node) ----------------
// 8-edge batches, sh[p][k] staging; inner h reads via LDS.128 (two packs/load,
// two acc chains); pairs beyond m skipped in remainder batches.
__global__ void k_edges(const int* __restrict__ ei, const float* __restrict__ ea,
                        const float* __restrict__ w1, const float* __restrict__ b1,
                        const float* __restrict__ b2) {
    __shared__ float su[DIM];
    __shared__ float2 sea[8];
    __shared__ int sdst[8];
    __shared__ ull sh[4][HID];
    __shared__ ull red[16 * 33];
    int s = blockIdx.x;
    int lo = g_rowptr[s], hi = g_rowptr[s + 1];
    if (lo >= hi) return;
    int t = threadIdx.x;
    int kq = t >> 5, o = t & 31;

    float w1c0 = __ldg(&w1[t]), w1c1 = __ldg(&w1[HID + t]), b1c = __ldg(&b1[t]);
    if (t < DIM) su[t] = g_out[s * DIM + t];
    __syncthreads();

    float ub = 0.f;
#pragma unroll
    for (int d = 0; d < DIM; d++) ub += su[d] * __ldg(&b2[d * DIM + o]);

    ull vp[32];
    const float* Vs = g_V + (size_t)s * KDIM + kq * 32 * 32 + o;
#pragma unroll
    for (int kk = 0; kk < 32; kk++) {
        float v = Vs[kk * 32];
        vp[kk] = pk2(v, v);
    }

    for (int base = lo; base < hi; base += 8) {
        int m = hi - base; if (m > 8) m = 8;
        __syncthreads();
        if (t < m) {
            int e = g_eids[base + t];
            sea[t] = *(const float2*)&ea[2 * e];
            sdst[t] = ei[EE + e];
        }
        __syncthreads();
#pragma unroll
        for (int p = 0; p < 4; p++) {
            float h0 = 0.f, h1 = 0.f;
            if (2 * p < m) {
                float v = sea[2 * p].x * w1c0 + sea[2 * p].y * w1c1 + b1c;
                h0 = v > 0.f ? v : 0.f;
            }
            if (2 * p + 1 < m) {
                float v = sea[2 * p + 1].x * w1c0 + sea[2 * p + 1].y * w1c1 + b1c;
                h1 = v > 0.f ? v : 0.f;
            }
            sh[p][t] = pk2(h0, h1);
        }
        __syncthreads();
#pragma unroll
        for (int p = 0; p < 4; p++) {
            if (2 * p < m) {
                ull acc0 = 0, acc1 = 0;
                const ulonglong2* shp = (const ulonglong2*)&sh[p][kq * 32];
#pragma unroll
                for (int kk = 0; kk < 16; kk++) {
                    ulonglong2 hh = shp[kk];
                    acc0 = ffma2(hh.x, vp[2 * kk], acc0);
                    acc1 = ffma2(hh.y, vp[2 * kk + 1], acc1);
                }
                red[(p * 4 + kq) * 33 + o] = add2(acc0, acc1);
            }
        }
        __syncthreads();
        {
            int p = kq;
            if (2 * p < m) {
                ull sum = add2(add2(red[(p * 4 + 0) * 33 + o], red[(p * 4 + 1) * 33 + o]),
                               add2(red[(p * 4 + 2) * 33 + o], red[(p * 4 + 3) * 33 + o]));
                float2 ms = upk2(sum);
                atomicAdd(&g_agg[sdst[2 * p] * DIM + o], ms.x + ub);
                if (2 * p + 1 < m) atomicAdd(&g_agg[sdst[2 * p + 1] * DIM + o], ms.y + ub);
            }
        }
    }
}

// ---------------- node update: mean + root + GRU (re-zeroes g_agg) ----------------
__global__ void k_update(const float* __restrict__ rootw,
                         const float* __restrict__ convb,
                         const float* __restrict__ wih,
                         const float* __restrict__ whh,
                         const float* __restrict__ bih,
                         const float* __restrict__ bhh) {
    __shared__ float Msm[8][DIM];
    int n = blockIdx.x * 8 + (threadIdx.x >> 5);
    int o = threadIdx.x & 31;
    int nl = threadIdx.x >> 5;

    float aggv = g_agg[n * DIM + o];
    g_agg[n * DIM + o] = 0.f;
    float agg = aggv / g_deg[n];
    float mo = agg + __ldg(&convb[o]);
#pragma unroll
    for (int d = 0; d < DIM; d++) mo += g_out[n * DIM + d] * __ldg(&rootw[d * DIM + o]);
    mo = mo > 0.f ? mo : 0.f;
    Msm[nl][o] = mo;
    __syncthreads();

    float ir = __ldg(&bih[o]), iz = __ldg(&bih[32 + o]), inn = __ldg(&bih[64 + o]);
    float hr = __ldg(&bhh[o]), hz = __ldg(&bhh[32 + o]), hn = __ldg(&bhh[64 + o]);
#pragma unroll
    for (int d = 0; d < DIM; d++) {
        float md = Msm[nl][d];
        float hd = g_out[n * DIM + d];
        ir += md * __ldg(&wih[d * 96 + o]);
        iz += md * __ldg(&wih[d * 96 + 32 + o]);
        inn += md * __ldg(&wih[d * 96 + 64 + o]);
        hr += hd * __ldg(&whh[d * 96 + o]);
        hz += hd * __ldg(&whh[d * 96 + 32 + o]);
        hn += hd * __ldg(&whh[d * 96 + 64 + o]);
    }
    float r = sigm(ir + hr);
    float z = sigm(iz + hz);
    float nv = tanhf(inn + r * hn);
    float hold = g_out[n * DIM + o];
    float hnew = (1.f - z) * nv + z * hold;
    __syncwarp();
    g_out[n * DIM + o] = hnew;
}

// ---------------- Set2Set: fused LSTM + attention (+ final MLP on last step) ----------------
__global__ void k_s2s(int step, int last,
                      const float* __restrict__ wih, const float* __restrict__ whh,
                      const float* __restrict__ bih, const float* __restrict__ bhh,
                      const float* __restrict__ l1w, const float* __restrict__ l1b,
                      const float* __restrict__ l2w, const float* __restrict__ l2b,
                      float* __restrict__ yout) {
    __shared__ float gs[128];
    __shared__ float sqh[32];
    __shared__ float rfin[32];
    __shared__ float ebuf[4096];
    __shared__ float wred[8];
    __shared__ float rpart[8][32];
    __shared__ float s_bmax, s_den;
    int b = blockIdx.x;
    int tid = threadIdx.x;
    int w = tid >> 5, lane = tid & 31;

    if (tid < 128) {
        float g = __ldg(&bih[tid]) + __ldg(&bhh[tid]);
        if (step > 0) {
#pragma unroll
            for (int t = 0; t < 2 * DIM; t++)
                g += g_qstar[b * 2 * DIM + t] * __ldg(&wih[t * 128 + tid]);
#pragma unroll
            for (int t = 0; t < DIM; t++)
                g += g_qh[b * DIM + t] * __ldg(&whh[t * 128 + tid]);
        }
        gs[tid] = g;
    }
    __syncthreads();
    if (tid < 32) {
        float qc_old = (step > 0) ? g_qc[b * DIM + tid] : 0.f;
        float qc = sigm(gs[32 + tid]) * qc_old + sigm(gs[tid]) * tanhf(gs[64 + tid]);
        g_qc[b * DIM + tid] = qc;
        float qh = sigm(gs[96 + tid]) * tanhf(qc);
        g_qh[b * DIM + tid] = qh;
        sqh[tid] = qh;
    }
    __syncthreads();

    int lo = g_gptr[b], hi = g_gptr[b + 1];
    int cnt = hi - lo;

    float mymax = -1e30f;
    for (int i = lo + w; i < hi; i += 8) {
        float v = g_out[(size_t)i * DIM + lane] * sqh[lane];
#pragma unroll
        for (int off = 16; off; off >>= 1) v += __shfl_xor_sync(0xffffffffu, v, off);
        if (lane == 0) ebuf[i - lo] = v;
        mymax = fmaxf(mymax, v);
    }
    if (lane == 0) wred[w] = mymax;
    __syncthreads();
    if (tid == 0) {
        float m = -1e30f;
        for (int q = 0; q < 8; q++) m = fmaxf(m, wred[q]);
        s_bmax = m;
    }
    __syncthreads();
    float bm = s_bmax;

    float ssum = 0.f;
    for (int idx = tid; idx < cnt; idx += 256) {
        float ev = expf(ebuf[idx] - bm);
        ebuf[idx] = ev;
        ssum += ev;
    }
#pragma unroll
    for (int off = 16; off; off >>= 1) ssum += __shfl_xor_sync(0xffffffffu, ssum, off);
    if (lane == 0) wred[w] = ssum;
    __syncthreads();
    if (tid == 0) {
        float tt = 0.f;
        for (int q = 0; q < 8; q++) tt += wred[q];
        s_den = tt;
    }
    __syncthreads();
    float invden = (cnt > 0 && s_den > 0.f) ? 1.f / s_den : 0.f;

    float rl = 0.f;
    for (int i = lo + w; i < hi; i += 8) {
        float a = ebuf[i - lo] * invden;
        rl += a * g_out[(size_t)i * DIM + lane];
    }
    rpart[w][lane] = rl;
    __syncthreads();
    if (w == 0) {
        float r = 0.f;
#pragma unroll
        for (int q = 0; q < 8; q++) r += rpart[q][lane];
        rfin[lane] = r;
        g_qstar[b * 2 * DIM + 32 + lane] = r;
        g_qstar[b * 2 * DIM + lane] = sqh[lane];
    }

    if (last) {
        __syncthreads();
        if (tid < 32) {
            int j = tid;
            float hj = __ldg(&l1b[j]);
#pragma unroll
            for (int t = 0; t < DIM; t++) hj += sqh[t] * __ldg(&l1w[t * DIM + j]);
#pragma unroll
            for (int t = 0; t < DIM; t++) hj += rfin[t] * __ldg(&l1w[(DIM + t) * DIM + j]);
            hj = hj > 0.f ? hj : 0.f;
            float v = hj * __ldg(&l2w[j]);
#pragma unroll
            for (int off = 16; off; off >>= 1) v += __shfl_xor_sync(0xffffffffu, v, off);
            if (j == 0) yout[b] = v + __ldg(&l2b[0]);
        }
    }
}

// ---------------- launch ----------------
extern "C" void kernel_launch(void* const* d_in, const int* in_sizes, int n_in,
                              void* d_out, int out_size) {
    const float* x       = (const float*)d_in[0];
    const float* ea      = (const float*)d_in[1];
    const float* lin0w   = (const float*)d_in[2];
    const float* lin0b   = (const float*)d_in[3];
    const float* ennw1   = (const float*)d_in[4];
    const float* ennb1   = (const float*)d_in[5];
    const float* ennw2   = (const float*)d_in[6];
    const float* ennb2   = (const float*)d_in[7];
    const float* rootw   = (const float*)d_in[8];
    const float* convb   = (const float*)d_in[9];
    const float* gruwih  = (const float*)d_in[10];
    const float* gruwhh  = (const float*)d_in[11];
    const float* grubih  = (const float*)d_in[12];
    const float* grubhh  = (const float*)d_in[13];
    const float* s2swih  = (const float*)d_in[14];
    const float* s2swhh  = (const float*)d_in[15];
    const float* s2sbih  = (const float*)d_in[16];
    const float* s2sbhh  = (const float*)d_in[17];
    const float* lin1w   = (const float*)d_in[18];
    const float* lin1b   = (const float*)d_in[19];
    const float* lin2w   = (const float*)d_in[20];
    const float* lin2b   = (const float*)d_in[21];
    const int*   ei      = (const int*)d_in[22];
    const int*   batch   = (const int*)d_in[23];
    float* yout = (float*)d_out;

    k_zeroinit<<<(NN * DIM + 1023) / 1024, 1024>>>(x, lin0w, lin0b);
    k_count<<<(EE + 255) / 256, 256>>>(ei);
    k_scan<<<1, 1024>>>();
    k_fill<<<(EE + 255) / 256, 256>>>(ei, batch);

    for (int it = 0; it < NMP; it++) {
        k_vgemm<<<2048, 256>>>(ennw2);
        k_edges<<<NN, 128>>>(ei, ea, ennw1, ennb1, ennb2);
        k_update<<<NN / 8, 256>>>(rootw, convb, gruwih, gruwhh, grubih, grubhh);
    }

    for (int s = 0; s < S2S; s++) {
        k_s2s<<<BG, 256>>>(s, s == S2S - 1 ? 1 : 0,
                           s2swih, s2swhh, s2sbih, s2sbhh,
                           lin1w, lin1b, lin2w, lin2b, yout);
    }
}

// round 15
// speedup vs baseline: 1.0781x; 1.0327x over previous
#include <cuda_runtime.h>
#include <math.h>

#define NN 8192
#define EE 131072
#define DIM 32
#define HID 128
#define BG 64
#define NMP 3
#define S2S 3
#define KDIM 4096   // HID*DIM

typedef unsigned long long ull;

__device__ __forceinline__ ull pk2(float lo, float hi) {
    ull r; asm("mov.b64 %0,{%1,%2};" : "=l"(r) : "f"(lo), "f"(hi)); return r;
}
__device__ __forceinline__ float2 upk2(ull v) {
    float2 r; asm("mov.b64 {%0,%1},%2;" : "=f"(r.x), "=f"(r.y) : "l"(v)); return r;
}
__device__ __forceinline__ ull ffma2(ull a, ull b, ull c) {
    ull d; asm("fma.rn.f32x2 %0,%1,%2,%3;" : "=l"(d) : "l"(a), "l"(b), "l"(c)); return d;
}
__device__ __forceinline__ ull add2(ull a, ull b) {
    ull d; asm("add.rn.f32x2 %0,%1,%2;" : "=l"(d) : "l"(a), "l"(b)); return d;
}

// ---------------- scratch (device globals; no allocation) ----------------
// invariant: g_cnt/g_dcnt/g_agg are ZERO at entry of every run (BSS-zeroed at
// load; k_scan re-zeroes cnt/dcnt, k_update re-zeroes agg each run).
__device__ float g_out[NN * DIM];            // node features / GRU hidden
__device__ float g_V[(size_t)NN * KDIM];     // V[s][k][o]
__device__ float g_agg[NN * DIM];            // atomic message accum
__device__ int   g_cnt[NN];
__device__ int   g_dcnt[NN];
__device__ int   g_rowptr[NN + 1];
__device__ int   g_woff[NN];
__device__ int   g_eids[EE];
__device__ float g_deg[NN];
__device__ int   g_gptr[BG + 1];

__device__ __forceinline__ float sigm(float x) { return 1.0f / (1.0f + expf(-x)); }

// ---------------- setup ----------------
// launch 0: edge counting (cnt/dcnt pre-zeroed by previous run / BSS) + lin0 init.
// grid 1024x256 = 262144 threads: first EE do atomics, all NN*DIM do node init.
__global__ void k_count(const int* __restrict__ ei,
                        const float* __restrict__ x,
                        const float* __restrict__ w0,
                        const float* __restrict__ b0) {
    int idx = blockIdx.x * blockDim.x + threadIdx.x;
    if (idx < EE) {
        atomicAdd(&g_cnt[ei[idx]], 1);          // src (CSR grouping)
        atomicAdd(&g_dcnt[ei[EE + idx]], 1);    // dst (degree for mean)
    }
    if (idx < NN * DIM) {
        int n = idx >> 5, j = idx & 31;
        float v = x[n] * w0[j] + b0[j];
        g_out[idx] = v > 0.f ? v : 0.f;
    }
}

// launch 1: shfl scan of src counts -> rowptr/woff; deg from dcnt;
// re-zeroes cnt/dcnt for the NEXT run.
__global__ void k_scan() {
    __shared__ int wsum[32], wscan[32];
    int t = threadIdx.x, lane = t & 31, wid = t >> 5;
    int base = t * 8;
    int v[8]; int csum = 0;
#pragma unroll
    for (int i = 0; i < 8; i++) { v[i] = g_cnt[base + i]; csum += v[i]; }
    int inc = csum;
#pragma unroll
    for (int off = 1; off < 32; off <<= 1) {
        int nv = __shfl_up_sync(0xffffffffu, inc, off);
        if (lane >= off) inc += nv;
    }
    if (lane == 31) wsum[wid] = inc;
    __syncthreads();
    if (t < 32) {
        int w = wsum[t];
#pragma unroll
        for (int off = 1; off < 32; off <<= 1) {
            int nv = __shfl_up_sync(0xffffffffu, w, off);
            if (t >= off) w += nv;
        }
        wscan[t] = w;
    }
    __syncthreads();
    int run = inc - csum + (wid > 0 ? wscan[wid - 1] : 0);
#pragma unroll
    for (int i = 0; i < 8; i++) {
        g_rowptr[base + i] = run;
        g_woff[base + i] = run;
        run += v[i];
        g_cnt[base + i] = 0;                  // ready for next run
    }
    if (t == 1023) g_rowptr[NN] = run;
#pragma unroll
    for (int i = 0; i < 8; i++) {
        int d = g_dcnt[base + i];
        g_deg[base + i] = (float)(d > 0 ? d : 1);
        g_dcnt[base + i] = 0;                 // ready for next run
    }
}

// launch 2: CSR fill, 1 edge/thread (+ per-graph ranges in block 0)
__global__ void k_fill(const int* __restrict__ ei, const int* __restrict__ batch) {
    int e = blockIdx.x * blockDim.x + threadIdx.x;
    if (e < EE) {
        int src = ei[e];
        int pos = atomicAdd(&g_woff[src], 1);
        g_eids[pos] = e;
    }
    if (blockIdx.x == 0 && threadIdx.x <= BG) {
        int b = threadIdx.x;
        int lo = 0, hi = NN;
        while (lo < hi) {
            int mid = (lo + hi) >> 1;
            if (batch[mid] < b) lo = mid + 1; else hi = mid;
        }
        g_gptr[b] = lo;
    }
}

// ---------------- V GEMM: V[N,4096] = out[N,32] @ B[32,4096] ----------------
// launch 3 (the ncu-profiled slot). grid 2048 = 128 node-tiles x 16 r-chunks.
__global__ void k_vgemm(const float* __restrict__ w2) {
    __shared__ ull  At2[64][32];    // [n][d] pk2(a,a)   16KB
    __shared__ float Bs[32][256];   // [d][rr]           32KB
    int tid = threadIdx.x;
    int ntile = blockIdx.x & 127;
    int rchunk = blockIdx.x >> 7;
    int rbase = rchunk * 256;
    int nodebase = ntile * 64;

#pragma unroll
    for (int i = 0; i < 8; i++) {
        int s = i * 256 + tid;
        int n = s >> 5, d = s & 31;
        float a = g_out[(nodebase + n) * DIM + d];
        At2[n][d] = pk2(a, a);
    }
#pragma unroll
    for (int i = 0; i < 8; i++) {
        int s = i * 256 + tid;
        int d = s >> 6, rq = s & 63;
        int r = rbase + rq * 4;
        int k = r >> 5, o = r & 31;
        *(float4*)&Bs[d][rq * 4] = *(const float4*)&w2[(size_t)k * 1024 + d * 32 + o];
    }
    __syncthreads();

    int w = tid >> 5, l = tid & 31;
    ull acc[8][4];
#pragma unroll
    for (int j = 0; j < 8; j++)
#pragma unroll
        for (int q = 0; q < 4; q++) acc[j][q] = 0ull;

#pragma unroll 4
    for (int d = 0; d < 32; d++) {
        ull b0 = *(const ull*)&Bs[d][2 * l];
        ull b1 = *(const ull*)&Bs[d][64 + 2 * l];
        ull b2 = *(const ull*)&Bs[d][128 + 2 * l];
        ull b3 = *(const ull*)&Bs[d][192 + 2 * l];
#pragma unroll
        for (int j = 0; j < 8; j++) {
            ull a = At2[w + 8 * j][d];
            acc[j][0] = ffma2(a, b0, acc[j][0]);
            acc[j][1] = ffma2(a, b1, acc[j][1]);
            acc[j][2] = ffma2(a, b2, acc[j][2]);
            acc[j][3] = ffma2(a, b3, acc[j][3]);
        }
    }
#pragma unroll
    for (int j = 0; j < 8; j++) {
        int n = nodebase + w + 8 * j;
        float* Vr = g_V + (size_t)n * KDIM + rbase;
#pragma unroll
        for (int q = 0; q < 4; q++) {
            float2 v = upk2(acc[j][q]);
            *(float2*)&Vr[64 * q + 2 * l] = v;
        }
    }
}

// ---------------- edge contraction + scatter (per src node) ----------------
__global__ void k_edges(const int* __restrict__ ei, const float* __restrict__ ea,
                        const float* __restrict__ w1, const float* __restrict__ b1,
                        const float* __restrict__ b2) {
    __shared__ float su[DIM];
    __shared__ float2 sea[8];
    __shared__ int sdst[8];
    __shared__ ull sh[4][HID];
    __shared__ ull red[16 * 33];
    int s = blockIdx.x;
    int lo = g_rowptr[s], hi = g_rowptr[s + 1];
    if (lo >= hi) return;
    int t = threadIdx.x;
    int kq = t >> 5, o = t & 31;

    float w1c0 = __ldg(&w1[t]), w1c1 = __ldg(&w1[HID + t]), b1c = __ldg(&b1[t]);
    if (t < DIM) su[t] = g_out[s * DIM + t];
    __syncthreads();

    float ub = 0.f;
#pragma unroll
    for (int d = 0; d < DIM; d++) ub += su[d] * __ldg(&b2[d * DIM + o]);

    ull vp[32];
    const float* Vs = g_V + (size_t)s * KDIM + kq * 32 * 32 + o;
#pragma unroll
    for (int kk = 0; kk < 32; kk++) {
        float v = Vs[kk * 32];
        vp[kk] = pk2(v, v);
    }

    for (int base = lo; base < hi; base += 8) {
        int m = hi - base; if (m > 8) m = 8;
        __syncthreads();
        if (t < m) {
            int e = g_eids[base + t];
            sea[t] = *(const float2*)&ea[2 * e];
            sdst[t] = ei[EE + e];
        }
        __syncthreads();
#pragma unroll
        for (int p = 0; p < 4; p++) {
            float h0 = 0.f, h1 = 0.f;
            if (2 * p < m) {
                float v = sea[2 * p].x * w1c0 + sea[2 * p].y * w1c1 + b1c;
                h0 = v > 0.f ? v : 0.f;
            }
            if (2 * p + 1 < m) {
                float v = sea[2 * p + 1].x * w1c0 + sea[2 * p + 1].y * w1c1 + b1c;
                h1 = v > 0.f ? v : 0.f;
            }
            sh[p][t] = pk2(h0, h1);
        }
        __syncthreads();
#pragma unroll
        for (int p = 0; p < 4; p++) {
            if (2 * p < m) {
                ull acc0 = 0, acc1 = 0;
                const ulonglong2* shp = (const ulonglong2*)&sh[p][kq * 32];
#pragma unroll
                for (int kk = 0; kk < 16; kk++) {
                    ulonglong2 hh = shp[kk];
                    acc0 = ffma2(hh.x, vp[2 * kk], acc0);
                    acc1 = ffma2(hh.y, vp[2 * kk + 1], acc1);
                }
                red[(p * 4 + kq) * 33 + o] = add2(acc0, acc1);
            }
        }
        __syncthreads();
        {
            int p = kq;
            if (2 * p < m) {
                ull sum = add2(add2(red[(p * 4 + 0) * 33 + o], red[(p * 4 + 1) * 33 + o]),
                               add2(red[(p * 4 + 2) * 33 + o], red[(p * 4 + 3) * 33 + o]));
                float2 ms = upk2(sum);
                atomicAdd(&g_agg[sdst[2 * p] * DIM + o], ms.x + ub);
                if (2 * p + 1 < m) atomicAdd(&g_agg[sdst[2 * p + 1] * DIM + o], ms.y + ub);
            }
        }
    }
}

// ---------------- node update: mean + root + GRU (re-zeroes g_agg) ----------------
__global__ void k_update(const float* __restrict__ rootw,
                         const float* __restrict__ convb,
                         const float* __restrict__ wih,
                         const float* __restrict__ whh,
                         const float* __restrict__ bih,
                         const float* __restrict__ bhh) {
    __shared__ float Msm[8][DIM];
    int n = blockIdx.x * 8 + (threadIdx.x >> 5);
    int o = threadIdx.x & 31;
    int nl = threadIdx.x >> 5;

    float aggv = g_agg[n * DIM + o];
    g_agg[n * DIM + o] = 0.f;
    float agg = aggv / g_deg[n];
    float mo = agg + __ldg(&convb[o]);
#pragma unroll
    for (int d = 0; d < DIM; d++) mo += g_out[n * DIM + d] * __ldg(&rootw[d * DIM + o]);
    mo = mo > 0.f ? mo : 0.f;
    Msm[nl][o] = mo;
    __syncthreads();

    float ir = __ldg(&bih[o]), iz = __ldg(&bih[32 + o]), inn = __ldg(&bih[64 + o]);
    float hr = __ldg(&bhh[o]), hz = __ldg(&bhh[32 + o]), hn = __ldg(&bhh[64 + o]);
#pragma unroll
    for (int d = 0; d < DIM; d++) {
        float md = Msm[nl][d];
        float hd = g_out[n * DIM + d];
        ir += md * __ldg(&wih[d * 96 + o]);
        iz += md * __ldg(&wih[d * 96 + 32 + o]);
        inn += md * __ldg(&wih[d * 96 + 64 + o]);
        hr += hd * __ldg(&whh[d * 96 + o]);
        hz += hd * __ldg(&whh[d * 96 + 32 + o]);
        hn += hd * __ldg(&whh[d * 96 + 64 + o]);
    }
    float r = sigm(ir + hr);
    float z = sigm(iz + hz);
    float nv = tanhf(inn + r * hn);
    float hold = g_out[n * DIM + o];
    float hnew = (1.f - z) * nv + z * hold;
    __syncwarp();
    g_out[n * DIM + o] = hnew;
}

// ---------------- Set2Set: ALL steps + final MLP in one kernel ----------------
// Graphs are independent: block b keeps qh/qc/qstar in smem across steps.
__global__ void k_s2s_all(const float* __restrict__ wih, const float* __restrict__ whh,
                          const float* __restrict__ bih, const float* __restrict__ bhh,
                          const float* __restrict__ l1w, const float* __restrict__ l1b,
                          const float* __restrict__ l2w, const float* __restrict__ l2b,
                          float* __restrict__ yout) {
    __shared__ float gs[128];
    __shared__ float sqh[32];
    __shared__ float sqc[32];
    __shared__ float sqstar[64];
    __shared__ float rfin[32];
    __shared__ float ebuf[4096];
    __shared__ float wred[8];
    __shared__ float rpart[8][32];
    __shared__ float s_bmax, s_den;
    int b = blockIdx.x;
    int tid = threadIdx.x;
    int w = tid >> 5, lane = tid & 31;
    int lo = g_gptr[b], hi = g_gptr[b + 1];
    int cnt = hi - lo;

    for (int step = 0; step < S2S; step++) {
        // --- LSTM cell ---
        if (tid < 128) {
            float g = __ldg(&bih[tid]) + __ldg(&bhh[tid]);
            if (step > 0) {
#pragma unroll
                for (int t = 0; t < 2 * DIM; t++)
                    g += sqstar[t] * __ldg(&wih[t * 128 + tid]);
#pragma unroll
                for (int t = 0; t < DIM; t++)
                    g += sqh[t] * __ldg(&whh[t * 128 + tid]);
            }
            gs[tid] = g;
        }
        __syncthreads();
        if (tid < 32) {
            float qc_old = (step > 0) ? sqc[tid] : 0.f;
            float qc = sigm(gs[32 + tid]) * qc_old + sigm(gs[tid]) * tanhf(gs[64 + tid]);
            sqc[tid] = qc;
            sqh[tid] = sigm(gs[96 + tid]) * tanhf(qc);
        }
        __syncthreads();

        // --- attention / readout ---
        float mymax = -1e30f;
        for (int i = lo + w; i < hi; i += 8) {
            float v = g_out[(size_t)i * DIM + lane] * sqh[lane];
#pragma unroll
            for (int off = 16; off; off >>= 1) v += __shfl_xor_sync(0xffffffffu, v, off);
            if (lane == 0) ebuf[i - lo] = v;
            mymax = fmaxf(mymax, v);
        }
        if (lane == 0) wred[w] = mymax;
        __syncthreads();
        if (tid == 0) {
            float m = -1e30f;
            for (int q = 0; q < 8; q++) m = fmaxf(m, wred[q]);
            s_bmax = m;
        }
        __syncthreads();
        float bm = s_bmax;

        float ssum = 0.f;
        for (int idx = tid; idx < cnt; idx += 256) {
            float ev = expf(ebuf[idx] - bm);
            ebuf[idx] = ev;
            ssum += ev;
        }
#pragma unroll
        for (int off = 16; off; off >>= 1) ssum += __shfl_xor_sync(0xffffffffu, ssum, off);
        if (lane == 0) wred[w] = ssum;
        __syncthreads();
        if (tid == 0) {
            float tt = 0.f;
            for (int q = 0; q < 8; q++) tt += wred[q];
            s_den = tt;
        }
        __syncthreads();
        float invden = (cnt > 0 && s_den > 0.f) ? 1.f / s_den : 0.f;

        float rl = 0.f;
        for (int i = lo + w; i < hi; i += 8) {
            float a = ebuf[i - lo] * invden;
            rl += a * g_out[(size_t)i * DIM + lane];
        }
        rpart[w][lane] = rl;
        __syncthreads();
        if (w == 0) {
            float r = 0.f;
#pragma unroll
            for (int q = 0; q < 8; q++) r += rpart[q][lane];
            rfin[lane] = r;
            sqstar[32 + lane] = r;
            sqstar[lane] = sqh[lane];
        }
        __syncthreads();
    }

    // --- final MLP ---
    if (tid < 32) {
        int j = tid;
        float hj = __ldg(&l1b[j]);
#pragma unroll
        for (int t = 0; t < DIM; t++) hj += sqh[t] * __ldg(&l1w[t * DIM + j]);
#pragma unroll
        for (int t = 0; t < DIM; t++) hj += rfin[t] * __ldg(&l1w[(DIM + t) * DIM + j]);
        hj = hj > 0.f ? hj : 0.f;
        float v = hj * __ldg(&l2w[j]);
#pragma unroll
        for (int off = 16; off; off >>= 1) v += __shfl_xor_sync(0xffffffffu, v, off);
        if (j == 0) yout[b] = v + __ldg(&l2b[0]);
    }
}

// ---------------- launch ----------------
extern "C" void kernel_launch(void* const* d_in, const int* in_sizes, int n_in,
                              void* d_out, int out_size) {
    const float* x       = (const float*)d_in[0];
    const float* ea      = (const float*)d_in[1];
    const float* lin0w   = (const float*)d_in[2];
    const float* lin0b   = (const float*)d_in[3];
    const float* ennw1   = (const float*)d_in[4];
    const float* ennb1   = (const float*)d_in[5];
    const float* ennw2   = (const float*)d_in[6];
    const float* ennb2   = (const float*)d_in[7];
    const float* rootw   = (const float*)d_in[8];
    const float* convb   = (const float*)d_in[9];
    const float* gruwih  = (const float*)d_in[10];
    const float* gruwhh  = (const float*)d_in[11];
    const float* grubih  = (const float*)d_in[12];
    const float* grubhh  = (const float*)d_in[13];
    const float* s2swih  = (const float*)d_in[14];
    const float* s2swhh  = (const float*)d_in[15];
    const float* s2sbih  = (const float*)d_in[16];
    const float* s2sbhh  = (const float*)d_in[17];
    const float* lin1w   = (const float*)d_in[18];
    const float* lin1b   = (const float*)d_in[19];
    const float* lin2w   = (const float*)d_in[20];
    const float* lin2b   = (const float*)d_in[21];
    const int*   ei      = (const int*)d_in[22];
    const int*   batch   = (const int*)d_in[23];
    float* yout = (float*)d_out;

    k_count<<<(NN * DIM + 255) / 256, 256>>>(ei, x, lin0w, lin0b);
    k_scan<<<1, 1024>>>();
    k_fill<<<(EE + 255) / 256, 256>>>(ei, batch);

    for (int it = 0; it < NMP; it++) {
        k_vgemm<<<2048, 256>>>(ennw2);
        k_edges<<<NN, 128>>>(ei, ea, ennw1, ennb1, ennb2);
        k_update<<<NN / 8, 256>>>(rootw, convb, gruwih, gruwhh, grubih, grubhh);
    }

    k_s2s_all<<<BG, 256>>>(s2swih, s2swhh, s2sbih, s2sbhh,
                           lin1w, lin1b, lin2w, lin2b, yout);
}

// round 17
// speedup vs baseline: 1.0839x; 1.0053x over previous
#include <cuda_runtime.h>
#include <math.h>

#define NN 8192
#define EE 131072
#define DIM 32
#define HID 128
#define BG 64
#define NMP 3
#define S2S 3
#define KDIM 4096   // HID*DIM

typedef unsigned long long ull;

__device__ __forceinline__ ull pk2(float lo, float hi) {
    ull r; asm("mov.b64 %0,{%1,%2};" : "=l"(r) : "f"(lo), "f"(hi)); return r;
}
__device__ __forceinline__ float2 upk2(ull v) {
    float2 r; asm("mov.b64 {%0,%1},%2;" : "=f"(r.x), "=f"(r.y) : "l"(v)); return r;
}
__device__ __forceinline__ ull ffma2(ull a, ull b, ull c) {
    ull d; asm("fma.rn.f32x2 %0,%1,%2,%3;" : "=l"(d) : "l"(a), "l"(b), "l"(c)); return d;
}
__device__ __forceinline__ ull add2(ull a, ull b) {
    ull d; asm("add.rn.f32x2 %0,%1,%2;" : "=l"(d) : "l"(a), "l"(b)); return d;
}

// ---------------- scratch (device globals; no allocation) ----------------
// invariant: g_cnt/g_dcnt/g_agg are ZERO at entry of every run (BSS-zeroed at
// load; k_scan re-zeroes cnt/dcnt, k_update re-zeroes agg each run).
__device__ float g_out[NN * DIM];            // node features / GRU hidden
__device__ float g_V[(size_t)NN * KDIM];     // V[s][k][o]
__device__ float g_agg[NN * DIM];            // atomic message accum
__device__ int   g_cnt[NN];
__device__ int   g_dcnt[NN];
__device__ int   g_rowptr[NN + 1];
__device__ int   g_woff[NN];
__device__ int   g_eids[EE];
__device__ float g_deg[NN];
__device__ int   g_gptr[BG + 1];

__device__ __forceinline__ float sigm(float x) { return 1.0f / (1.0f + expf(-x)); }

// ---------------- setup ----------------
__global__ void k_count(const int* __restrict__ ei,
                        const float* __restrict__ x,
                        const float* __restrict__ w0,
                        const float* __restrict__ b0) {
    int idx = blockIdx.x * blockDim.x + threadIdx.x;
    if (idx < EE) {
        atomicAdd(&g_cnt[ei[idx]], 1);          // src (CSR grouping)
        atomicAdd(&g_dcnt[ei[EE + idx]], 1);    // dst (degree for mean)
    }
    if (idx < NN * DIM) {
        int n = idx >> 5, j = idx & 31;
        float v = x[n] * w0[j] + b0[j];
        g_out[idx] = v > 0.f ? v : 0.f;
    }
}

__global__ void k_scan() {
    __shared__ int wsum[32], wscan[32];
    int t = threadIdx.x, lane = t & 31, wid = t >> 5;
    int base = t * 8;
    int v[8]; int csum = 0;
#pragma unroll
    for (int i = 0; i < 8; i++) { v[i] = g_cnt[base + i]; csum += v[i]; }
    int inc = csum;
#pragma unroll
    for (int off = 1; off < 32; off <<= 1) {
        int nv = __shfl_up_sync(0xffffffffu, inc, off);
        if (lane >= off) inc += nv;
    }
    if (lane == 31) wsum[wid] = inc;
    __syncthreads();
    if (t < 32) {
        int w = wsum[t];
#pragma unroll
        for (int off = 1; off < 32; off <<= 1) {
            int nv = __shfl_up_sync(0xffffffffu, w, off);
            if (t >= off) w += nv;
        }
        wscan[t] = w;
    }
    __syncthreads();
    int run = inc - csum + (wid > 0 ? wscan[wid - 1] : 0);
#pragma unroll
    for (int i = 0; i < 8; i++) {
        g_rowptr[base + i] = run;
        g_woff[base + i] = run;
        run += v[i];
        g_cnt[base + i] = 0;                  // ready for next run
    }
    if (t == 1023) g_rowptr[NN] = run;
#pragma unroll
    for (int i = 0; i < 8; i++) {
        int d = g_dcnt[base + i];
        g_deg[base + i] = (float)(d > 0 ? d : 1);
        g_dcnt[base + i] = 0;                 // ready for next run
    }
}

__global__ void k_fill(const int* __restrict__ ei, const int* __restrict__ batch) {
    int e = blockIdx.x * blockDim.x + threadIdx.x;
    if (e < EE) {
        int src = ei[e];
        int pos = atomicAdd(&g_woff[src], 1);
        g_eids[pos] = e;
    }
    if (blockIdx.x == 0 && threadIdx.x <= BG) {
        int b = threadIdx.x;
        int lo = 0, hi = NN;
        while (lo < hi) {
            int mid = (lo + hi) >> 1;
            if (batch[mid] < b) lo = mid + 1; else hi = mid;
        }
        g_gptr[b] = lo;
    }
}

// ---------------- V GEMM: V[N,4096] = out[N,32] @ B[32,4096] ----------------
// grid 2048 = 128 node-tiles x 16 r-chunks (256 cols each); block 256.
// A packs stored permuted At2b[d][(n&7)*8+(n>>3)] so each thread reads its
// 8 A-packs per d with 4x broadcast LDS.128 (was 8x LDS.64).
__global__ void k_vgemm(const float* __restrict__ w2) {
    __shared__ ull  At2b[32][66];   // [d][w*8+j] pk2(a,a); 528B rows (16B-aligned)
    __shared__ float Bs[32][256];   // [d][rr]
    int tid = threadIdx.x;
    int ntile = blockIdx.x & 127;
    int rchunk = blockIdx.x >> 7;
    int rbase = rchunk * 256;
    int nodebase = ntile * 64;

#pragma unroll
    for (int i = 0; i < 8; i++) {
        int s = i * 256 + tid;
        int n = s >> 5, d = s & 31;
        float a = g_out[(nodebase + n) * DIM + d];
        At2b[d][(n & 7) * 8 + (n >> 3)] = pk2(a, a);
    }
#pragma unroll
    for (int i = 0; i < 8; i++) {
        int s = i * 256 + tid;
        int d = s >> 6, rq = s & 63;
        int r = rbase + rq * 4;
        int k = r >> 5, o = r & 31;
        *(float4*)&Bs[d][rq * 4] = *(const float4*)&w2[(size_t)k * 1024 + d * 32 + o];
    }
    __syncthreads();

    int w = tid >> 5, l = tid & 31;
    ull acc[8][4];
#pragma unroll
    for (int j = 0; j < 8; j++)
#pragma unroll
        for (int q = 0; q < 4; q++) acc[j][q] = 0ull;

#pragma unroll 4
    for (int d = 0; d < 32; d++) {
        ull b0 = *(const ull*)&Bs[d][2 * l];
        ull b1 = *(const ull*)&Bs[d][64 + 2 * l];
        ull b2 = *(const ull*)&Bs[d][128 + 2 * l];
        ull b3 = *(const ull*)&Bs[d][192 + 2 * l];
        const ulonglong2* ap2 = (const ulonglong2*)&At2b[d][w * 8];
        ulonglong2 a01 = ap2[0];
        ulonglong2 a23 = ap2[1];
        ulonglong2 a45 = ap2[2];
        ulonglong2 a67 = ap2[3];
        ull aj[8] = { a01.x, a01.y, a23.x, a23.y, a45.x, a45.y, a67.x, a67.y };
#pragma unroll
        for (int j = 0; j < 8; j++) {
            acc[j][0] = ffma2(aj[j], b0, acc[j][0]);
            acc[j][1] = ffma2(aj[j], b1, acc[j][1]);
            acc[j][2] = ffma2(aj[j], b2, acc[j][2]);
            acc[j][3] = ffma2(aj[j], b3, acc[j][3]);
        }
    }
#pragma unroll
    for (int j = 0; j < 8; j++) {
        int n = nodebase + w + 8 * j;
        float* Vr = g_V + (size_t)n * KDIM + rbase;
#pragma unroll
        for (int q = 0; q < 4; q++) {
            float2 v = upk2(acc[j][q]);
            *(float2*)&Vr[64 * q + 2 * l] = v;
        }
    }
}

// ---------------- edge contraction + scatter (per src node) ----------------
__global__ void k_edges(const int* __restrict__ ei, const float* __restrict__ ea,
                        const float* __restrict__ w1, const float* __restrict__ b1,
                        const float* __restrict__ b2) {
    __shared__ float su[DIM];
    __shared__ float2 sea[8];
    __shared__ int sdst[8];
    __shared__ ull sh[4][HID];
    __shared__ ull red[16 * 33];
    int s = blockIdx.x;
    int lo = g_rowptr[s], hi = g_rowptr[s + 1];
    if (lo >= hi) return;
    int t = threadIdx.x;
    int kq = t >> 5, o = t & 31;

    float w1c0 = __ldg(&w1[t]), w1c1 = __ldg(&w1[HID + t]), b1c = __ldg(&b1[t]);
    if (t < DIM) su[t] = g_out[s * DIM + t];
    __syncthreads();

    float ub = 0.f;
#pragma unroll
    for (int d = 0; d < DIM; d++) ub += su[d] * __ldg(&b2[d * DIM + o]);

    ull vp[32];
    const float* Vs = g_V + (size_t)s * KDIM + kq * 32 * 32 + o;
#pragma unroll
    for (int kk = 0; kk < 32; kk++) {
        float v = Vs[kk * 32];
        vp[kk] = pk2(v, v);
    }

    for (int base = lo; base < hi; base += 8) {
        int m = hi - base; if (m > 8) m = 8;
        __syncthreads();
        if (t < m) {
            int e = g_eids[base + t];
            sea[t] = *(const float2*)&ea[2 * e];
            sdst[t] = ei[EE + e];
        }
        __syncthreads();
#pragma unroll
        for (int p = 0; p < 4; p++) {
            float h0 = 0.f, h1 = 0.f;
            if (2 * p < m) {
                float v = sea[2 * p].x * w1c0 + sea[2 * p].y * w1c1 + b1c;
                h0 = v > 0.f ? v : 0.f;
            }
            if (2 * p + 1 < m) {
                float v = sea[2 * p + 1].x * w1c0 + sea[2 * p + 1].y * w1c1 + b1c;
                h1 = v > 0.f ? v : 0.f;
            }
            sh[p][t] = pk2(h0, h1);
        }
        __syncthreads();
#pragma unroll
        for (int p = 0; p < 4; p++) {
            if (2 * p < m) {
                ull acc0 = 0, acc1 = 0;
                const ulonglong2* shp = (const ulonglong2*)&sh[p][kq * 32];
#pragma unroll
                for (int kk = 0; kk < 16; kk++) {
                    ulonglong2 hh = shp[kk];
                    acc0 = ffma2(hh.x, vp[2 * kk], acc0);
                    acc1 = ffma2(hh.y, vp[2 * kk + 1], acc1);
                }
                red[(p * 4 + kq) * 33 + o] = add2(acc0, acc1);
            }
        }
        __syncthreads();
        {
            int p = kq;
            if (2 * p < m) {
                ull sum = add2(add2(red[(p * 4 + 0) * 33 + o], red[(p * 4 + 1) * 33 + o]),
                               add2(red[(p * 4 + 2) * 33 + o], red[(p * 4 + 3) * 33 + o]));
                float2 ms = upk2(sum);
                atomicAdd(&g_agg[sdst[2 * p] * DIM + o], ms.x + ub);
                if (2 * p + 1 < m) atomicAdd(&g_agg[sdst[2 * p + 1] * DIM + o], ms.y + ub);
            }
        }
    }
}

// ---------------- node update: mean + root + GRU (re-zeroes g_agg) ----------------
__global__ void k_update(const float* __restrict__ rootw,
                         const float* __restrict__ convb,
                         const float* __restrict__ wih,
                         const float* __restrict__ whh,
                         const float* __restrict__ bih,
                         const float* __restrict__ bhh) {
    __shared__ float Msm[8][DIM];
    int n = blockIdx.x * 8 + (threadIdx.x >> 5);
    int o = threadIdx.x & 31;
    int nl = threadIdx.x >> 5;

    float aggv = g_agg[n * DIM + o];
    g_agg[n * DIM + o] = 0.f;
    float agg = aggv / g_deg[n];
    float mo = agg + __ldg(&convb[o]);
#pragma unroll
    for (int d = 0; d < DIM; d++) mo += g_out[n * DIM + d] * __ldg(&rootw[d * DIM + o]);
    mo = mo > 0.f ? mo : 0.f;
    Msm[nl][o] = mo;
    __syncthreads();

    float ir = __ldg(&bih[o]), iz = __ldg(&bih[32 + o]), inn = __ldg(&bih[64 + o]);
    float hr = __ldg(&bhh[o]), hz = __ldg(&bhh[32 + o]), hn = __ldg(&bhh[64 + o]);
#pragma unroll
    for (int d = 0; d < DIM; d++) {
        float md = Msm[nl][d];
        float hd = g_out[n * DIM + d];
        ir += md * __ldg(&wih[d * 96 + o]);
        iz += md * __ldg(&wih[d * 96 + 32 + o]);
        inn += md * __ldg(&wih[d * 96 + 64 + o]);
        hr += hd * __ldg(&whh[d * 96 + o]);
        hz += hd * __ldg(&whh[d * 96 + 32 + o]);
        hn += hd * __ldg(&whh[d * 96 + 64 + o]);
    }
    float r = sigm(ir + hr);
    float z = sigm(iz + hz);
    float nv = tanhf(inn + r * hn);
    float hold = g_out[n * DIM + o];
    float hnew = (1.f - z) * nv + z * hold;
    __syncwarp();
    g_out[n * DIM + o] = hnew;
}

// ---------------- Set2Set: ALL steps + final MLP in one kernel ----------------
__global__ void k_s2s_all(const float* __restrict__ wih, const float* __restrict__ whh,
                          const float* __restrict__ bih, const float* __restrict__ bhh,
                          const float* __restrict__ l1w, const float* __restrict__ l1b,
                          const float* __restrict__ l2w, const float* __restrict__ l2b,
                          float* __restrict__ yout) {
    __shared__ float gs[128];
    __shared__ float sqh[32];
    __shared__ float sqc[32];
    __shared__ float sqstar[64];
    __shared__ float rfin[32];
    __shared__ float ebuf[4096];
    __shared__ float wred[8];
    __shared__ float rpart[8][32];
    __shared__ float s_bmax, s_den;
    int b = blockIdx.x;
    int tid = threadIdx.x;
    int w = tid >> 5, lane = tid & 31;
    int lo = g_gptr[b], hi = g_gptr[b + 1];
    int cnt = hi - lo;

    for (int step = 0; step < S2S; step++) {
        if (tid < 128) {
            float g = __ldg(&bih[tid]) + __ldg(&bhh[tid]);
            if (step > 0) {
#pragma unroll
                for (int t = 0; t < 2 * DIM; t++)
                    g += sqstar[t] * __ldg(&wih[t * 128 + tid]);
#pragma unroll
                for (int t = 0; t < DIM; t++)
                    g += sqh[t] * __ldg(&whh[t * 128 + tid]);
            }
            gs[tid] = g;
        }
        __syncthreads();
        if (tid < 32) {
            float qc_old = (step > 0) ? sqc[tid] : 0.f;
            float qc = sigm(gs[32 + tid]) * qc_old + sigm(gs[tid]) * tanhf(gs[64 + tid]);
            sqc[tid] = qc;
            sqh[tid] = sigm(gs[96 + tid]) * tanhf(qc);
        }
        __syncthreads();

        float mymax = -1e30f;
        for (int i = lo + w; i < hi; i += 8) {
            float v = g_out[(size_t)i * DIM + lane] * sqh[lane];
#pragma unroll
            for (int off = 16; off; off >>= 1) v += __shfl_xor_sync(0xffffffffu, v, off);
            if (lane == 0) ebuf[i - lo] = v;
            mymax = fmaxf(mymax, v);
        }
        if (lane == 0) wred[w] = mymax;
        __syncthreads();
        if (tid == 0) {
            float m = -1e30f;
            for (int q = 0; q < 8; q++) m = fmaxf(m, wred[q]);
            s_bmax = m;
        }
        __syncthreads();
        float bm = s_bmax;

        float ssum = 0.f;
        for (int idx = tid; idx < cnt; idx += 256) {
            float ev = expf(ebuf[idx] - bm);
            ebuf[idx] = ev;
            ssum += ev;
        }
#pragma unroll
        for (int off = 16; off; off >>= 1) ssum += __shfl_xor_sync(0xffffffffu, ssum, off);
        if (lane == 0) wred[w] = ssum;
        __syncthreads();
        if (tid == 0) {
            float tt = 0.f;
            for (int q = 0; q < 8; q++) tt += wred[q];
            s_den = tt;
        }
        __syncthreads();
        float invden = (cnt > 0 && s_den > 0.f) ? 1.f / s_den : 0.f;

        float rl = 0.f;
        for (int i = lo + w; i < hi; i += 8) {
            float a = ebuf[i - lo] * invden;
            rl += a * g_out[(size_t)i * DIM + lane];
        }
        rpart[w][lane] = rl;
        __syncthreads();
        if (w == 0) {
            float r = 0.f;
#pragma unroll
            for (int q = 0; q < 8; q++) r += rpart[q][lane];
            rfin[lane] = r;
            sqstar[32 + lane] = r;
            sqstar[lane] = sqh[lane];
        }
        __syncthreads();
    }

    if (tid < 32) {
        int j = tid;
        float hj = __ldg(&l1b[j]);
#pragma unroll
        for (int t = 0; t < DIM; t++) hj += sqh[t] * __ldg(&l1w[t * DIM + j]);
#pragma unroll
        for (int t = 0; t < DIM; t++) hj += rfin[t] * __ldg(&l1w[(DIM + t) * DIM + j]);
        hj = hj > 0.f ? hj : 0.f;
        float v = hj * __ldg(&l2w[j]);
#pragma unroll
        for (int off = 16; off; off >>= 1) v += __shfl_xor_sync(0xffffffffu, v, off);
        if (j == 0) yout[b] = v + __ldg(&l2b[0]);
    }
}

// ---------------- launch ----------------
extern "C" void kernel_launch(void* const* d_in, const int* in_sizes, int n_in,
                              void* d_out, int out_size) {
    const float* x       = (const float*)d_in[0];
    const float* ea      = (const float*)d_in[1];
    const float* lin0w   = (const float*)d_in[2];
    const float* lin0b   = (const float*)d_in[3];
    const float* ennw1   = (const float*)d_in[4];
    const float* ennb1   = (const float*)d_in[5];
    const float* ennw2   = (const float*)d_in[6];
    const float* ennb2   = (const float*)d_in[7];
    const float* rootw   = (const float*)d_in[8];
    const float* convb   = (const float*)d_in[9];
    const float* gruwih  = (const float*)d_in[10];
    const float* gruwhh  = (const float*)d_in[11];
    const float* grubih  = (const float*)d_in[12];
    const float* grubhh  = (const float*)d_in[13];
    const float* s2swih  = (const float*)d_in[14];
    const float* s2swhh  = (const float*)d_in[15];
    const float* s2sbih  = (const float*)d_in[16];
    const float* s2sbhh  = (const float*)d_in[17];
    const float* lin1w   = (const float*)d_in[18];
    const float* lin1b   = (const float*)d_in[19];
    const float* lin2w   = (const float*)d_in[20];
    const float* lin2b   = (const float*)d_in[21];
    const int*   ei      = (const int*)d_in[22];
    const int*   batch   = (const int*)d_in[23];
    float* yout = (float*)d_out;

    k_count<<<(NN * DIM + 255) / 256, 256>>>(ei, x, lin0w, lin0b);
    k_scan<<<1, 1024>>>();
    k_fill<<<(EE + 255) / 256, 256>>>(ei, batch);

    for (int it = 0; it < NMP; it++) {
        k_vgemm<<<2048, 256>>>(ennw2);
        k_edges<<<NN, 128>>>(ei, ea, ennw1, ennb1, ennb2);
        k_update<<<NN / 8, 256>>>(rootw, convb, gruwih, gruwhh, grubih, grubhh);
    }

    k_s2s_all<<<BG, 256>>>(s2swih, s2swhh, s2sbih, s2sbhh,
                           lin1w, lin1b, lin2w, lin2b, yout);
}